// round 14
// baseline (speedup 1.0000x reference)
#include <cuda_runtime.h>
#include <cuda_bf16.h>
#include <cstdint>

typedef __nv_bfloat16 bf16;

// ===================== scratch (device globals) =============================
#define NBZ 64
__device__ bf16 g_xT_h[(size_t)NBZ * 512 * 1024];
__device__ bf16 g_xT_l[(size_t)NBZ * 512 * 1024];
__device__ bf16 g_x_h [(size_t)NBZ * 1024 * 512];
__device__ bf16 g_x_l [(size_t)NBZ * 1024 * 512];
__device__ bf16 g_w1T_h[(size_t)16 * 512 * 512];
__device__ bf16 g_w1T_l[(size_t)16 * 512 * 512];
__device__ bf16 g_w2T_h[(size_t)16 * 512 * 512];
__device__ bf16 g_w2T_l[(size_t)16 * 512 * 512];
__device__ bf16 g_w3_h [(size_t)16 * 512 * 512];
__device__ bf16 g_w3_l [(size_t)16 * 512 * 512];
__device__ bf16 g_G_h [(size_t)NBZ * 512 * 512];
__device__ bf16 g_G_l [(size_t)NBZ * 512 * 512];
__device__ bf16 g_M2_h[(size_t)NBZ * 512 * 512];
__device__ bf16 g_M2_l[(size_t)NBZ * 512 * 512];
__device__ bf16 g_AsT_h[(size_t)NBZ * 512 * 512];
__device__ bf16 g_AsT_l[(size_t)NBZ * 512 * 512];
__device__ bf16 g_WT_h[(size_t)NBZ * 512 * 512];
__device__ bf16 g_WT_l[(size_t)NBZ * 512 * 512];
__device__ float g_L  [(size_t)NBZ * 512 * 512];

// symmetric-G tile LUT: 4x4 tiling of 128-tiles, upper triangle, 10 tiles
__device__ __constant__ int SYMBX[10] = {0,1,1,2,2,2,3,3,3,3};
__device__ __constant__ int SYMBY[10] = {0,0,1,0,1,2,0,1,2,3};
// mirror block pairs (bx > by): 6 pairs of 128x128 blocks
__device__ __constant__ int OFFX[6]   = {1,2,3,2,3,3};
__device__ __constant__ int OFFY[6]   = {0,0,0,1,1,2};

// ===================== helpers =============================================
__device__ __forceinline__ uint32_t smem_u32(const void* p) {
    uint32_t a;
    asm("{ .reg .u64 t; cvta.to.shared.u64 t, %1; cvt.u32.u64 %0, t; }"
        : "=r"(a) : "l"(p));
    return a;
}
__device__ __forceinline__ void cpa16(uint32_t s, const void* g) {
    asm volatile("cp.async.cg.shared.global [%0], [%1], 16;\n" :: "r"(s), "l"(g));
}
#define CPA_COMMIT() asm volatile("cp.async.commit_group;\n" ::: "memory")

#define LDSM_X4(r, a) \
    asm volatile("ldmatrix.sync.aligned.m8n8.x4.shared.b16 {%0,%1,%2,%3}, [%4];" \
        : "=r"((r)[0]), "=r"((r)[1]), "=r"((r)[2]), "=r"((r)[3]) : "r"(a))

#define MMA16816(d, a, b0, b1) \
    asm volatile("mma.sync.aligned.m16n8k16.row.col.f32.bf16.bf16.f32 " \
        "{%0,%1,%2,%3},{%4,%5,%6,%7},{%8,%9},{%0,%1,%2,%3};" \
        : "+f"((d)[0]), "+f"((d)[1]), "+f"((d)[2]), "+f"((d)[3]) \
        : "r"((a)[0]), "r"((a)[1]), "r"((a)[2]), "r"((a)[3]), "r"(b0), "r"(b1))

__device__ __forceinline__ void split2(float a, float b, uint32_t& hp, uint32_t& lp) {
    bf16 ha = __float2bfloat16_rn(a), hb = __float2bfloat16_rn(b);
    bf16 la = __float2bfloat16_rn(a - __bfloat162float(ha));
    bf16 lb = __float2bfloat16_rn(b - __bfloat162float(hb));
    hp = ((uint32_t)__bfloat16_as_ushort(hb) << 16) | __bfloat16_as_ushort(ha);
    lp = ((uint32_t)__bfloat16_as_ushort(lb) << 16) | __bfloat16_as_ushort(la);
}

// swizzled byte offset within a 128-row x 64B tile: row r, 16B-segment s
__device__ __forceinline__ uint32_t swz(int r, int s) {
    return (uint32_t)(r * 64 + ((s ^ ((r >> 1) & 3)) << 4));
}

// ===================== prepass: split (+ optional transpose) ================
template<bool STRAIGHT, bool TRANS>
__global__ void split_kernel(const float* __restrict__ in,
                             bf16* __restrict__ sh, bf16* __restrict__ sl,
                             bf16* __restrict__ th, bf16* __restrict__ tl,
                             int R, int C)
{
    __shared__ float tile[32][33];
    const int bz = blockIdx.z;
    const float* ib = in + (size_t)bz * R * C;
    const int c0 = blockIdx.x * 32, r0 = blockIdx.y * 32;
    const int tx = threadIdx.x, ty = threadIdx.y;  // 16 x 16

    #pragma unroll
    for (int ry = 0; ry < 2; ry++) {
        int r = ty * 2 + ry;
        float2 v = *(const float2*)(ib + (size_t)(r0 + r) * C + c0 + tx * 2);
        if (TRANS) { tile[tx * 2][r] = v.x; tile[tx * 2 + 1][r] = v.y; }
        if (STRAIGHT) {
            uint32_t hp, lp; split2(v.x, v.y, hp, lp);
            size_t o = ((size_t)bz * R * C + (size_t)(r0 + r) * C + c0 + tx * 2) >> 1;
            ((uint32_t*)sh)[o] = hp; ((uint32_t*)sl)[o] = lp;
        }
    }
    if (TRANS) {
        __syncthreads();
        #pragma unroll
        for (int cy = 0; cy < 2; cy++) {
            int c = ty * 2 + cy;
            float a = tile[c][tx * 2], b = tile[c][tx * 2 + 1];
            uint32_t hp, lp; split2(a, b, hp, lp);
            size_t o = ((size_t)bz * C * R + (size_t)(c0 + c) * R + r0 + tx * 2) >> 1;
            ((uint32_t*)th)[o] = hp; ((uint32_t*)tl)[o] = lp;
        }
    }
}

// ===================== bf16x3 GEMM (128x128 CTA, swizzled, 3-stage) =========
// C[bz][m][n] = sum_k A[m,k]*B[n,k]; A,B as bf16 hi/lo pairs, K-major.
// CTA tile 128x128, 256 threads (8 warps: 2m x 4n, warp tile 64x32),
// K-chunk 32 (=64B rows). Swizzled smem, 3 stages, ONE barrier per chunk,
// prefetch at end of chunk (round-11 winning position).
// Per kk: B frags first (16 regs), then per-mi A load feeding 12 MMAs
// (keeps peak regs ~110, under the 128 cap that sank round 12).
// smem 96 KB -> 2 CTAs/SM (16 warps). 2x MMAs per LDSM/cp.async vs 64x64.
#define TILE_B 8192                  // 128 rows x 64 B
#define STAGE_B (4 * TILE_B)         // Ah Al Bh Bl = 32768 B
#define NSTAGE 3
#define GEMM_SMEM (NSTAGE * STAGE_B) // 98304 B

template<bool SPLIT_OUT, bool SYM>
__global__ void __launch_bounds__(256, 2)
gemm_bf16x3(const bf16* __restrict__ Ah, const bf16* __restrict__ Al,
            const bf16* __restrict__ Bh, const bf16* __restrict__ Bl,
            float* __restrict__ Cf, bf16* __restrict__ Ch, bf16* __restrict__ Cl,
            int K, int M, int Nt, int aMod, int bMod)
{
    extern __shared__ bf16 smem[];
    const uint32_t sbase = smem_u32(smem);
    const int tid = threadIdx.x;
    const int wid = tid >> 5, lane = tid & 31;
    const int wm = wid & 1, wn = wid >> 1;      // 2x4 warps, 64x32 each
    const int bz = blockIdx.z;
    const int bx = SYM ? SYMBX[blockIdx.x] : (int)blockIdx.x;
    const int by = SYM ? SYMBY[blockIdx.x] : (int)blockIdx.y;

    const size_t aOff = (size_t)(bz % aMod) * M * K + (size_t)by * 128 * K;
    const size_t bOff = (size_t)(bz % bMod) * Nt * K + (size_t)bx * 128 * K;
    const bf16* gp[4] = { Ah + aOff, Al + aOff, Bh + bOff, Bl + bOff };

    float acc[4][4][4];
    #pragma unroll
    for (int mi = 0; mi < 4; mi++)
        #pragma unroll
        for (int nj = 0; nj < 4; nj++)
            #pragma unroll
            for (int e = 0; e < 4; e++) acc[mi][nj][e] = 0.0f;

    auto load_chunk = [&](int t, int s) {
        const uint32_t st = sbase + s * STAGE_B;
        const int k0 = t * 32;
        #pragma unroll
        for (int i = 0; i < 8; i++) {
            int idx = tid + i * 256;            // 0..2047
            int tile = idx >> 9;                // 512 16B-vectors per tile
            int rem  = idx & 511;
            int r    = rem >> 2;                // 0..127
            int seg  = rem & 3;
            cpa16(st + tile * TILE_B + swz(r, seg),
                  gp[tile] + (size_t)r * K + k0 + seg * 8);
        }
    };

    const int T = K / 32;
    load_chunk(0, 0); CPA_COMMIT();
    load_chunk(1, 1); CPA_COMMIT();

    const int row16 = lane & 15;
    const int hi16  = lane >> 4;

    for (int t = 0; t < T; t++) {
        if (t + 1 < T) asm volatile("cp.async.wait_group 1;" ::: "memory");
        else           asm volatile("cp.async.wait_group 0;" ::: "memory");
        __syncthreads();                        // single barrier per chunk

        const uint32_t st = sbase + (t % NSTAGE) * STAGE_B;

        #pragma unroll
        for (int kk = 0; kk < 2; kk++) {
            const int s = kk * 2 + hi16;
            // B fragments first (16 regs live)
            uint32_t bh[2][4], bl[2][4];
            #pragma unroll
            for (int g = 0; g < 2; g++) {
                const int r = wn * 32 + g * 16 + row16;
                uint32_t bd = st + 2 * TILE_B + swz(r, s);
                LDSM_X4(bh[g], bd);
                LDSM_X4(bl[g], bd + TILE_B);
            }
            // per-mi: 2 LDSM feed 12 MMAs (keeps live regs low)
            #pragma unroll
            for (int mi = 0; mi < 4; mi++) {
                const int r = wm * 64 + mi * 16 + row16;
                uint32_t ad = st + swz(r, s);
                uint32_t ah[4], al[4];
                LDSM_X4(ah, ad);
                LDSM_X4(al, ad + TILE_B);
                #pragma unroll
                for (int nj = 0; nj < 4; nj++) {
                    const int g = nj >> 1, o = nj & 1;
                    MMA16816(acc[mi][nj], ah, bl[g][o], bl[g][o + 2]); // h*l
                    MMA16816(acc[mi][nj], al, bh[g][o], bh[g][o + 2]); // l*h
                    MMA16816(acc[mi][nj], ah, bh[g][o], bh[g][o + 2]); // h*h
                }
            }
        }
        // prefetch at end of chunk (round-11 winning position)
        if (t + 2 < T) { load_chunk(t + 2, (t + 2) % NSTAGE); CPA_COMMIT(); }
    }

    // ---- epilogue ----
    const int gr = lane >> 2, cp = (lane & 3) * 2;
    const size_t cBase = (size_t)bz * M * Nt;
    #pragma unroll
    for (int mi = 0; mi < 4; mi++)
        #pragma unroll
        for (int nj = 0; nj < 4; nj++) {
            const int m0 = by * 128 + wm * 64 + mi * 16 + gr;
            const int n  = bx * 128 + wn * 32 + nj * 8 + cp;
            if (SPLIT_OUT) {
                uint32_t hp, lp;
                split2(acc[mi][nj][0], acc[mi][nj][1], hp, lp);
                ((uint32_t*)Ch)[(cBase + (size_t)m0 * Nt + n) >> 1] = hp;
                ((uint32_t*)Cl)[(cBase + (size_t)m0 * Nt + n) >> 1] = lp;
                split2(acc[mi][nj][2], acc[mi][nj][3], hp, lp);
                ((uint32_t*)Ch)[(cBase + (size_t)(m0 + 8) * Nt + n) >> 1] = hp;
                ((uint32_t*)Cl)[(cBase + (size_t)(m0 + 8) * Nt + n) >> 1] = lp;
            } else {
                *(float2*)(Cf + cBase + (size_t)m0 * Nt + n) =
                    make_float2(acc[mi][nj][0], acc[mi][nj][1]);
                *(float2*)(Cf + cBase + (size_t)(m0 + 8) * Nt + n) =
                    make_float2(acc[mi][nj][2], acc[mi][nj][3]);
            }
        }
}

// ===================== mirror lower triangle of symmetric G =================
// 6 off-diagonal 128x128 blocks (upper) -> transposed lower, h and l arrays.
__global__ void mirror_sym(bf16* __restrict__ Gh, bf16* __restrict__ Gl) {
    __shared__ ushort tile[32][33];
    const int t = blockIdx.x;          // 0..95
    const int pair = t >> 4, sub = t & 15;
    const int r0 = OFFY[pair] * 128 + (sub >> 2) * 32;  // source rows (upper)
    const int c0 = OFFX[pair] * 128 + (sub & 3) * 32;   // source cols
    const size_t base = (size_t)blockIdx.y * 512 * 512;
    const int tx = threadIdx.x, ty = threadIdx.y;       // 16 x 16

    #pragma unroll
    for (int p = 0; p < 2; p++) {
        bf16* arr = p ? Gl : Gh;
        #pragma unroll
        for (int ry = 0; ry < 2; ry++) {
            int r = ty * 2 + ry;
            uint32_t v = ((const uint32_t*)arr)[(base + (size_t)(r0 + r) * 512 + c0 + tx * 2) >> 1];
            tile[tx * 2][r] = (ushort)(v & 0xffff);
            tile[tx * 2 + 1][r] = (ushort)(v >> 16);
        }
        __syncthreads();
        #pragma unroll
        for (int cy = 0; cy < 2; cy++) {
            int c = ty * 2 + cy;
            uint32_t o = (uint32_t)tile[c][tx * 2] | ((uint32_t)tile[c][tx * 2 + 1] << 16);
            ((uint32_t*)arr)[(base + (size_t)(c0 + c) * 512 + r0 + tx * 2) >> 1] = o;
        }
        __syncthreads();
    }
}

// ===================== fused softmax + transpose + split ====================
// smem row stride 513 floats; all smem stores SCALAR (rows not f4-aligned).
#define SMX_SMEM (32 * 513 * 4)
__global__ void __launch_bounds__(256)
softmaxT_split(const float* __restrict__ L,
               bf16* __restrict__ th, bf16* __restrict__ tl)
{
    extern __shared__ float buf[];                 // [32][513]
    const int bz = blockIdx.y, r0 = blockIdx.x * 32;
    const float* Lb = L + ((size_t)bz * 512 + r0) * 512;
    const int tid = threadIdx.x, w = tid >> 5, lane = tid & 31;

    #pragma unroll
    for (int i = 0; i < 4; i++) {
        const int r = w * 4 + i;
        const float4* rp = (const float4*)(Lb + (size_t)r * 512);
        float4 v[4];
        #pragma unroll
        for (int j = 0; j < 4; j++) v[j] = rp[j * 32 + lane];

        float m = -3.4e38f;
        #pragma unroll
        for (int j = 0; j < 4; j++)
            m = fmaxf(m, fmaxf(fmaxf(v[j].x, v[j].y), fmaxf(v[j].z, v[j].w)));
        #pragma unroll
        for (int o = 16; o > 0; o >>= 1) m = fmaxf(m, __shfl_xor_sync(~0u, m, o));

        float s = 0.0f;
        #pragma unroll
        for (int j = 0; j < 4; j++) {
            v[j].x = __expf(v[j].x - m); v[j].y = __expf(v[j].y - m);
            v[j].z = __expf(v[j].z - m); v[j].w = __expf(v[j].w - m);
            s += v[j].x + v[j].y + v[j].z + v[j].w;
        }
        #pragma unroll
        for (int o = 16; o > 0; o >>= 1) s += __shfl_xor_sync(~0u, s, o);
        const float inv = 1.0f / s;

        #pragma unroll
        for (int j = 0; j < 4; j++) {
            const int c = (j * 32 + lane) * 4;
            buf[r * 513 + c]     = v[j].x * inv;
            buf[r * 513 + c + 1] = v[j].y * inv;
            buf[r * 513 + c + 2] = v[j].z * inv;
            buf[r * 513 + c + 3] = v[j].w * inv;
        }
    }
    __syncthreads();

    const int cg = tid >> 4, rp = (tid & 15) * 2;
    #pragma unroll 4
    for (int iter = 0; iter < 32; iter++) {
        const int c = iter * 16 + cg;
        uint32_t hp, lp;
        split2(buf[rp * 513 + c], buf[(rp + 1) * 513 + c], hp, lp);
        const size_t o = (((size_t)bz * 512 + c) * 512 + r0 + rp) >> 1;
        ((uint32_t*)th)[o] = hp;
        ((uint32_t*)tl)[o] = lp;
    }
}

// ===================== launch ===============================================
extern "C" void kernel_launch(void* const* d_in, const int* in_sizes, int n_in,
                              void* d_out, int out_size)
{
    const float* x  = (const float*)d_in[0];  // [4,16,1024,512]
    const float* w1 = (const float*)d_in[1];  // [16,512,512]
    const float* w2 = (const float*)d_in[2];
    const float* w3 = (const float*)d_in[3];
    float* out = (float*)d_out;

    bf16 *xT_h, *xT_l, *x_h, *x_l, *w1T_h, *w1T_l, *w2T_h, *w2T_l, *w3_h, *w3_l;
    bf16 *G_h, *G_l, *M2_h, *M2_l, *AsT_h, *AsT_l, *WT_h, *WT_l;
    float* L;
    cudaGetSymbolAddress((void**)&xT_h, g_xT_h); cudaGetSymbolAddress((void**)&xT_l, g_xT_l);
    cudaGetSymbolAddress((void**)&x_h,  g_x_h ); cudaGetSymbolAddress((void**)&x_l,  g_x_l );
    cudaGetSymbolAddress((void**)&w1T_h, g_w1T_h); cudaGetSymbolAddress((void**)&w1T_l, g_w1T_l);
    cudaGetSymbolAddress((void**)&w2T_h, g_w2T_h); cudaGetSymbolAddress((void**)&w2T_l, g_w2T_l);
    cudaGetSymbolAddress((void**)&w3_h,  g_w3_h ); cudaGetSymbolAddress((void**)&w3_l,  g_w3_l );
    cudaGetSymbolAddress((void**)&G_h,  g_G_h ); cudaGetSymbolAddress((void**)&G_l,  g_G_l );
    cudaGetSymbolAddress((void**)&M2_h, g_M2_h); cudaGetSymbolAddress((void**)&M2_l, g_M2_l);
    cudaGetSymbolAddress((void**)&AsT_h, g_AsT_h); cudaGetSymbolAddress((void**)&AsT_l, g_AsT_l);
    cudaGetSymbolAddress((void**)&WT_h, g_WT_h); cudaGetSymbolAddress((void**)&WT_l, g_WT_l);
    cudaGetSymbolAddress((void**)&L, g_L);

    cudaFuncSetAttribute(gemm_bf16x3<true , true >, cudaFuncAttributeMaxDynamicSharedMemorySize, GEMM_SMEM);
    cudaFuncSetAttribute(gemm_bf16x3<true , false>, cudaFuncAttributeMaxDynamicSharedMemorySize, GEMM_SMEM);
    cudaFuncSetAttribute(gemm_bf16x3<false, false>, cudaFuncAttributeMaxDynamicSharedMemorySize, GEMM_SMEM);
    cudaFuncSetAttribute(softmaxT_split, cudaFuncAttributeMaxDynamicSharedMemorySize, SMX_SMEM);

    dim3 tb(16, 16);
    dim3 blk(256);
    dim3 g512(4, 4, NBZ);    // M = N = 512, 128-tiles
    dim3 gOut(4, 8, NBZ);    // M = 1024, N = 512

    // launch 0-2: splits needed by G
    split_kernel<true, true ><<<dim3(16, 32, NBZ), tb>>>(x, x_h, x_l, xT_h, xT_l, 1024, 512);
    split_kernel<false, true><<<dim3(16, 16, 16), tb>>>(w1, nullptr, nullptr, w1T_h, w1T_l, 512, 512);
    split_kernel<false, true><<<dim3(16, 16, 16), tb>>>(w2, nullptr, nullptr, w2T_h, w2T_l, 512, 512);
    // launch 3 (ncu capture target): G upper triangle (10/16 tiles)
    gemm_bf16x3<true, true ><<<dim3(10, 1, NBZ), blk, GEMM_SMEM>>>(
        xT_h, xT_l, xT_h, xT_l, nullptr, G_h, G_l, 1024, 512, 512, NBZ, NBZ);
    // launch 4: mirror lower triangle of G
    mirror_sym<<<dim3(96, NBZ), tb>>>(G_h, G_l);
    // launch 5: w3 split (needed at launch 9)
    split_kernel<true, false><<<dim3(16, 16, 16), tb>>>(w3, w3_h, w3_l, nullptr, nullptr, 512, 512);
    // launch 6: M2[d'][a] = sum_b w2T[d',b] G[a,b]
    gemm_bf16x3<true, false><<<g512, blk, GEMM_SMEM>>>(
        w2T_h, w2T_l, G_h, G_l, nullptr, M2_h, M2_l, 512, 512, 512, 16, NBZ);
    // launch 7: L[h][d'] = sum_a w1T[h,a] M2[d',a]  (f32 out)
    gemm_bf16x3<false, false><<<g512, blk, GEMM_SMEM>>>(
        w1T_h, w1T_l, M2_h, M2_l, L, nullptr, nullptr, 512, 512, 512, 16, NBZ);
    // launch 8: fused softmax rows + transpose + split -> AsT[d'][h]
    softmaxT_split<<<dim3(16, NBZ), dim3(256), SMX_SMEM>>>(L, AsT_h, AsT_l);
    // launch 9: WT[d'][d] = sum_h AsT[d',h] w3[d,h]
    gemm_bf16x3<true, false><<<g512, blk, GEMM_SMEM>>>(
        AsT_h, AsT_l, w3_h, w3_l, nullptr, WT_h, WT_l, 512, 512, 512, NBZ, 16);
    // launch 10: out[n][d'] = sum_d x[n,d] WT[d',d]  (M=1024)
    gemm_bf16x3<false, false><<<gOut, blk, GEMM_SMEM>>>(
        x_h, x_l, WT_h, WT_l, out, nullptr, nullptr, 512, 1024, 512, NBZ, NBZ);
}

// round 16
// speedup vs baseline: 1.1293x; 1.1293x over previous
#include <cuda_runtime.h>
#include <cuda_bf16.h>
#include <cstdint>

typedef __nv_bfloat16 bf16;

// ===================== scratch (device globals) =============================
#define NBZ 64
__device__ bf16 g_xT_h[(size_t)NBZ * 512 * 1024];
__device__ bf16 g_xT_l[(size_t)NBZ * 512 * 1024];
__device__ bf16 g_x_h [(size_t)NBZ * 1024 * 512];
__device__ bf16 g_x_l [(size_t)NBZ * 1024 * 512];
__device__ bf16 g_w1T_h[(size_t)16 * 512 * 512];
__device__ bf16 g_w1T_l[(size_t)16 * 512 * 512];
__device__ bf16 g_w2T_h[(size_t)16 * 512 * 512];
__device__ bf16 g_w2T_l[(size_t)16 * 512 * 512];
__device__ bf16 g_w3_h [(size_t)16 * 512 * 512];
__device__ bf16 g_w3_l [(size_t)16 * 512 * 512];
__device__ bf16 g_G_h [(size_t)NBZ * 512 * 512];
__device__ bf16 g_G_l [(size_t)NBZ * 512 * 512];
__device__ bf16 g_M2_h[(size_t)NBZ * 512 * 512];
__device__ bf16 g_M2_l[(size_t)NBZ * 512 * 512];
__device__ bf16 g_AsT_h[(size_t)NBZ * 512 * 512];
__device__ bf16 g_AsT_l[(size_t)NBZ * 512 * 512];
__device__ bf16 g_WT_h[(size_t)NBZ * 512 * 512];
__device__ bf16 g_WT_l[(size_t)NBZ * 512 * 512];
__device__ float g_L  [(size_t)NBZ * 512 * 512];

// symmetric-G tile LUT: 8x8 tiling of 64-tiles, upper triangle (bx >= by), 36 tiles
__device__ __constant__ int SYMBX8[36] =
    {0,1,1,2,2,2,3,3,3,3,4,4,4,4,4,5,5,5,5,5,5,6,6,6,6,6,6,6,7,7,7,7,7,7,7,7};
__device__ __constant__ int SYMBY8[36] =
    {0,0,1,0,1,2,0,1,2,3,0,1,2,3,4,0,1,2,3,4,5,0,1,2,3,4,5,6,0,1,2,3,4,5,6,7};
// mirror block pairs (bx > by): 28 pairs of 64x64 blocks
__device__ __constant__ int OFFX8[28] =
    {1,2,3,4,5,6,7,2,3,4,5,6,7,3,4,5,6,7,4,5,6,7,5,6,7,6,7,7};
__device__ __constant__ int OFFY8[28] =
    {0,0,0,0,0,0,0,1,1,1,1,1,1,2,2,2,2,2,3,3,3,3,4,4,4,5,5,6};

// ===================== helpers =============================================
__device__ __forceinline__ uint32_t smem_u32(const void* p) {
    uint32_t a;
    asm("{ .reg .u64 t; cvta.to.shared.u64 t, %1; cvt.u32.u64 %0, t; }"
        : "=r"(a) : "l"(p));
    return a;
}
__device__ __forceinline__ void cpa16(uint32_t s, const void* g) {
    asm volatile("cp.async.cg.shared.global [%0], [%1], 16;\n" :: "r"(s), "l"(g));
}

#define MBAR_INIT(a, c) \
    asm volatile("mbarrier.init.shared.b64 [%0], %1;" :: "r"(a), "r"((uint32_t)(c)) : "memory")
#define MBAR_ARRIVE(a) \
    asm volatile("mbarrier.arrive.shared.b64 _, [%0];" :: "r"(a) : "memory")
// .noinc: completion of this thread's prior cp.asyncs counts as ONE REAL
// arrival against the preset count. (Default variant nets zero — round-15 hang.)
#define CPA_MBAR_ARRIVE(a) \
    asm volatile("cp.async.mbarrier.arrive.noinc.shared.b64 [%0];" :: "r"(a) : "memory")
#define MBAR_WAIT(a, ph) do { \
    asm volatile("{ .reg .pred P1; WL_%=: mbarrier.try_wait.parity.acquire.cta.shared::cta.b64 P1, [%0], %1, 0x989680; @P1 bra.uni WD_%=; bra.uni WL_%=; WD_%=: }" \
        :: "r"(a), "r"((uint32_t)(ph)) : "memory"); } while (0)

#define LDSM_X4(r, a) \
    asm volatile("ldmatrix.sync.aligned.m8n8.x4.shared.b16 {%0,%1,%2,%3}, [%4];" \
        : "=r"((r)[0]), "=r"((r)[1]), "=r"((r)[2]), "=r"((r)[3]) : "r"(a))

#define MMA16816(d, a, b0, b1) \
    asm volatile("mma.sync.aligned.m16n8k16.row.col.f32.bf16.bf16.f32 " \
        "{%0,%1,%2,%3},{%4,%5,%6,%7},{%8,%9},{%0,%1,%2,%3};" \
        : "+f"((d)[0]), "+f"((d)[1]), "+f"((d)[2]), "+f"((d)[3]) \
        : "r"((a)[0]), "r"((a)[1]), "r"((a)[2]), "r"((a)[3]), "r"(b0), "r"(b1))

__device__ __forceinline__ void split2(float a, float b, uint32_t& hp, uint32_t& lp) {
    bf16 ha = __float2bfloat16_rn(a), hb = __float2bfloat16_rn(b);
    bf16 la = __float2bfloat16_rn(a - __bfloat162float(ha));
    bf16 lb = __float2bfloat16_rn(b - __bfloat162float(hb));
    hp = ((uint32_t)__bfloat16_as_ushort(hb) << 16) | __bfloat16_as_ushort(ha);
    lp = ((uint32_t)__bfloat16_as_ushort(lb) << 16) | __bfloat16_as_ushort(la);
}

// swizzled byte offset within a 64x64B tile: row r (0..63), 16B-segment s (0..3)
__device__ __forceinline__ uint32_t swz(int r, int s) {
    return (uint32_t)(r * 64 + ((s ^ ((r >> 1) & 3)) << 4));
}

// ===================== prepass: split (+ optional transpose) ================
template<bool STRAIGHT, bool TRANS>
__global__ void split_kernel(const float* __restrict__ in,
                             bf16* __restrict__ sh, bf16* __restrict__ sl,
                             bf16* __restrict__ th, bf16* __restrict__ tl,
                             int R, int C)
{
    __shared__ float tile[32][33];
    const int bz = blockIdx.z;
    const float* ib = in + (size_t)bz * R * C;
    const int c0 = blockIdx.x * 32, r0 = blockIdx.y * 32;
    const int tx = threadIdx.x, ty = threadIdx.y;  // 16 x 16

    #pragma unroll
    for (int ry = 0; ry < 2; ry++) {
        int r = ty * 2 + ry;
        float2 v = *(const float2*)(ib + (size_t)(r0 + r) * C + c0 + tx * 2);
        if (TRANS) { tile[tx * 2][r] = v.x; tile[tx * 2 + 1][r] = v.y; }
        if (STRAIGHT) {
            uint32_t hp, lp; split2(v.x, v.y, hp, lp);
            size_t o = ((size_t)bz * R * C + (size_t)(r0 + r) * C + c0 + tx * 2) >> 1;
            ((uint32_t*)sh)[o] = hp; ((uint32_t*)sl)[o] = lp;
        }
    }
    if (TRANS) {
        __syncthreads();
        #pragma unroll
        for (int cy = 0; cy < 2; cy++) {
            int c = ty * 2 + cy;
            float a = tile[c][tx * 2], b = tile[c][tx * 2 + 1];
            uint32_t hp, lp; split2(a, b, hp, lp);
            size_t o = ((size_t)bz * C * R + (size_t)(c0 + c) * R + r0 + tx * 2) >> 1;
            ((uint32_t*)th)[o] = hp; ((uint32_t*)tl)[o] = lp;
        }
    }
}

// ===================== bf16x3 GEMM (warp-specialized mbarrier pipeline) =====
// C[bz][m][n] = sum_k A[m,k]*B[n,k]; A,B as bf16 hi/lo pairs, K-major.
// CTA tile 64x64. 160 threads: warps 0-3 consumers (2x2 of 32x32 tiles),
// warp 4 producer (issues all cp.asyncs). 3 stages, full/empty mbarriers,
// NO __syncthreads in the mainloop — consumer warps decouple.
#define TILE_B 4096                  // 64 rows x 64 B
#define STAGE_B (4 * TILE_B)         // Ah Al Bh Bl = 16384 B
#define NSTAGE 3
#define MBAR_OFF (NSTAGE * STAGE_B)  // barriers after tiles
#define GEMM_SMEM (MBAR_OFF + NSTAGE * 16)  // 49200 B

template<bool SPLIT_OUT, bool SYM>
__global__ void __launch_bounds__(160, 4)
gemm_bf16x3(const bf16* __restrict__ Ah, const bf16* __restrict__ Al,
            const bf16* __restrict__ Bh, const bf16* __restrict__ Bl,
            float* __restrict__ Cf, bf16* __restrict__ Ch, bf16* __restrict__ Cl,
            int K, int M, int Nt, int aMod, int bMod)
{
    extern __shared__ bf16 smem[];
    const uint32_t sbase = smem_u32(smem);
    const int tid = threadIdx.x;
    const int wid = tid >> 5, lane = tid & 31;
    const int bz = blockIdx.z;
    const int bx = SYM ? SYMBX8[blockIdx.x] : (int)blockIdx.x;
    const int by = SYM ? SYMBY8[blockIdx.x] : (int)blockIdx.y;

    const size_t aOff = (size_t)(bz % aMod) * M * K + (size_t)by * 64 * K;
    const size_t bOff = (size_t)(bz % bMod) * Nt * K + (size_t)bx * 64 * K;
    const bf16* gp[4] = { Ah + aOff, Al + aOff, Bh + bOff, Bl + bOff };

    // mbarriers: interleaved [full0, empty0, full1, empty1, ...]
    auto mbF = [&](int s) { return sbase + MBAR_OFF + s * 16; };
    auto mbE = [&](int s) { return sbase + MBAR_OFF + s * 16 + 8; };

    if (tid == 0) {
        #pragma unroll
        for (int s = 0; s < NSTAGE; s++) {
            MBAR_INIT(mbF(s), 32);   // 32 producer-lane cp.async completions
            MBAR_INIT(mbE(s), 128);  // 128 consumer-thread arrivals
        }
    }
    __syncthreads();   // barriers visible before any use (only sync in kernel)

    const int T = K / 32;

    if (wid == 4) {
        // ---------------- producer warp ----------------
        int s = 0, ph = 1;                      // flipped phase: first NSTAGE
        for (int t = 0; t < T; t++) {           // empty-waits pass immediately
            MBAR_WAIT(mbE(s), ph);
            const uint32_t st = sbase + s * STAGE_B;
            const int k0 = t * 32;
            #pragma unroll
            for (int i = 0; i < 32; i++) {
                int v   = lane + i * 32;        // 0..1023
                int tile = v >> 8;
                int rem  = v & 255;
                int r    = rem >> 2;
                int seg  = rem & 3;
                cpa16(st + tile * TILE_B + swz(r, seg),
                      gp[tile] + (size_t)r * K + k0 + seg * 8);
            }
            CPA_MBAR_ARRIVE(mbF(s));            // .noinc: real arrival on completion
            if (++s == NSTAGE) { s = 0; ph ^= 1; }
        }
        return;
    }

    // ---------------- consumer warps (0-3) ----------------
    const int wm = wid & 1, wn = wid >> 1;      // 2x2 warps, 32x32 each
    const int row16 = lane & 15;
    const int hi16  = lane >> 4;

    float acc[2][4][4];
    #pragma unroll
    for (int mi = 0; mi < 2; mi++)
        #pragma unroll
        for (int nj = 0; nj < 4; nj++)
            #pragma unroll
            for (int e = 0; e < 4; e++) acc[mi][nj][e] = 0.0f;

    int s = 0, ph = 0;
    for (int t = 0; t < T; t++) {
        MBAR_WAIT(mbF(s), ph);
        const uint32_t st = sbase + s * STAGE_B;

        #pragma unroll
        for (int kk = 0; kk < 2; kk++) {
            const int sg = kk * 2 + hi16;
            uint32_t ah[2][4], al[2][4];
            #pragma unroll
            for (int mi = 0; mi < 2; mi++) {
                const int r = wm * 32 + mi * 16 + row16;
                uint32_t ad = st + swz(r, sg);
                LDSM_X4(ah[mi], ad);
                LDSM_X4(al[mi], ad + TILE_B);
            }
            uint32_t bh[2][4], bl[2][4];
            #pragma unroll
            for (int g = 0; g < 2; g++) {
                const int r = wn * 32 + g * 16 + row16;
                uint32_t bd = st + 2 * TILE_B + swz(r, sg);
                LDSM_X4(bh[g], bd);
                LDSM_X4(bl[g], bd + TILE_B);
            }
            #pragma unroll
            for (int mi = 0; mi < 2; mi++)
                #pragma unroll
                for (int nj = 0; nj < 4; nj++) {
                    const int g = nj >> 1, o = nj & 1;
                    MMA16816(acc[mi][nj], ah[mi], bl[g][o], bl[g][o + 2]); // h*l
                    MMA16816(acc[mi][nj], al[mi], bh[g][o], bh[g][o + 2]); // l*h
                    MMA16816(acc[mi][nj], ah[mi], bh[g][o], bh[g][o + 2]); // h*h
                }
        }
        MBAR_ARRIVE(mbE(s));                    // done reading stage s
        if (++s == NSTAGE) { s = 0; ph ^= 1; }
    }

    // ---- epilogue (consumers only) ----
    const int gr = lane >> 2, cp = (lane & 3) * 2;
    const size_t cBase = (size_t)bz * M * Nt;
    #pragma unroll
    for (int mi = 0; mi < 2; mi++)
        #pragma unroll
        for (int nj = 0; nj < 4; nj++) {
            const int m0 = by * 64 + wm * 32 + mi * 16 + gr;
            const int n  = bx * 64 + wn * 32 + nj * 8 + cp;
            if (SPLIT_OUT) {
                uint32_t hp, lp;
                split2(acc[mi][nj][0], acc[mi][nj][1], hp, lp);
                ((uint32_t*)Ch)[(cBase + (size_t)m0 * Nt + n) >> 1] = hp;
                ((uint32_t*)Cl)[(cBase + (size_t)m0 * Nt + n) >> 1] = lp;
                split2(acc[mi][nj][2], acc[mi][nj][3], hp, lp);
                ((uint32_t*)Ch)[(cBase + (size_t)(m0 + 8) * Nt + n) >> 1] = hp;
                ((uint32_t*)Cl)[(cBase + (size_t)(m0 + 8) * Nt + n) >> 1] = lp;
            } else {
                *(float2*)(Cf + cBase + (size_t)m0 * Nt + n) =
                    make_float2(acc[mi][nj][0], acc[mi][nj][1]);
                *(float2*)(Cf + cBase + (size_t)(m0 + 8) * Nt + n) =
                    make_float2(acc[mi][nj][2], acc[mi][nj][3]);
            }
        }
}

// ===================== mirror lower triangle of symmetric G =================
__global__ void mirror_sym(bf16* __restrict__ Gh, bf16* __restrict__ Gl) {
    __shared__ ushort tile[32][33];
    const int t = blockIdx.x;          // 0..111
    const int pair = t >> 2, sub = t & 3;
    const int r0 = OFFY8[pair] * 64 + (sub >> 1) * 32;  // source rows (upper)
    const int c0 = OFFX8[pair] * 64 + (sub & 1) * 32;   // source cols
    const size_t base = (size_t)blockIdx.y * 512 * 512;
    const int tx = threadIdx.x, ty = threadIdx.y;       // 16 x 16

    #pragma unroll
    for (int p = 0; p < 2; p++) {
        bf16* arr = p ? Gl : Gh;
        #pragma unroll
        for (int ry = 0; ry < 2; ry++) {
            int r = ty * 2 + ry;
            uint32_t v = ((const uint32_t*)arr)[(base + (size_t)(r0 + r) * 512 + c0 + tx * 2) >> 1];
            tile[tx * 2][r] = (ushort)(v & 0xffff);
            tile[tx * 2 + 1][r] = (ushort)(v >> 16);
        }
        __syncthreads();
        #pragma unroll
        for (int cy = 0; cy < 2; cy++) {
            int c = ty * 2 + cy;
            uint32_t o = (uint32_t)tile[c][tx * 2] | ((uint32_t)tile[c][tx * 2 + 1] << 16);
            ((uint32_t*)arr)[(base + (size_t)(c0 + c) * 512 + r0 + tx * 2) >> 1] = o;
        }
        __syncthreads();
    }
}

// ===================== fused softmax + transpose + split ====================
// smem row stride 513 floats; all smem stores SCALAR (rows not f4-aligned).
#define SMX_SMEM (32 * 513 * 4)
__global__ void __launch_bounds__(256)
softmaxT_split(const float* __restrict__ L,
               bf16* __restrict__ th, bf16* __restrict__ tl)
{
    extern __shared__ float buf[];                 // [32][513]
    const int bz = blockIdx.y, r0 = blockIdx.x * 32;
    const float* Lb = L + ((size_t)bz * 512 + r0) * 512;
    const int tid = threadIdx.x, w = tid >> 5, lane = tid & 31;

    #pragma unroll
    for (int i = 0; i < 4; i++) {
        const int r = w * 4 + i;
        const float4* rp = (const float4*)(Lb + (size_t)r * 512);
        float4 v[4];
        #pragma unroll
        for (int j = 0; j < 4; j++) v[j] = rp[j * 32 + lane];

        float m = -3.4e38f;
        #pragma unroll
        for (int j = 0; j < 4; j++)
            m = fmaxf(m, fmaxf(fmaxf(v[j].x, v[j].y), fmaxf(v[j].z, v[j].w)));
        #pragma unroll
        for (int o = 16; o > 0; o >>= 1) m = fmaxf(m, __shfl_xor_sync(~0u, m, o));

        float s = 0.0f;
        #pragma unroll
        for (int j = 0; j < 4; j++) {
            v[j].x = __expf(v[j].x - m); v[j].y = __expf(v[j].y - m);
            v[j].z = __expf(v[j].z - m); v[j].w = __expf(v[j].w - m);
            s += v[j].x + v[j].y + v[j].z + v[j].w;
        }
        #pragma unroll
        for (int o = 16; o > 0; o >>= 1) s += __shfl_xor_sync(~0u, s, o);
        const float inv = 1.0f / s;

        #pragma unroll
        for (int j = 0; j < 4; j++) {
            const int c = (j * 32 + lane) * 4;
            buf[r * 513 + c]     = v[j].x * inv;
            buf[r * 513 + c + 1] = v[j].y * inv;
            buf[r * 513 + c + 2] = v[j].z * inv;
            buf[r * 513 + c + 3] = v[j].w * inv;
        }
    }
    __syncthreads();

    const int cg = tid >> 4, rp = (tid & 15) * 2;
    #pragma unroll 4
    for (int iter = 0; iter < 32; iter++) {
        const int c = iter * 16 + cg;
        uint32_t hp, lp;
        split2(buf[rp * 513 + c], buf[(rp + 1) * 513 + c], hp, lp);
        const size_t o = (((size_t)bz * 512 + c) * 512 + r0 + rp) >> 1;
        ((uint32_t*)th)[o] = hp;
        ((uint32_t*)tl)[o] = lp;
    }
}

// ===================== launch ===============================================
extern "C" void kernel_launch(void* const* d_in, const int* in_sizes, int n_in,
                              void* d_out, int out_size)
{
    const float* x  = (const float*)d_in[0];  // [4,16,1024,512]
    const float* w1 = (const float*)d_in[1];  // [16,512,512]
    const float* w2 = (const float*)d_in[2];
    const float* w3 = (const float*)d_in[3];
    float* out = (float*)d_out;

    bf16 *xT_h, *xT_l, *x_h, *x_l, *w1T_h, *w1T_l, *w2T_h, *w2T_l, *w3_h, *w3_l;
    bf16 *G_h, *G_l, *M2_h, *M2_l, *AsT_h, *AsT_l, *WT_h, *WT_l;
    float* L;
    cudaGetSymbolAddress((void**)&xT_h, g_xT_h); cudaGetSymbolAddress((void**)&xT_l, g_xT_l);
    cudaGetSymbolAddress((void**)&x_h,  g_x_h ); cudaGetSymbolAddress((void**)&x_l,  g_x_l );
    cudaGetSymbolAddress((void**)&w1T_h, g_w1T_h); cudaGetSymbolAddress((void**)&w1T_l, g_w1T_l);
    cudaGetSymbolAddress((void**)&w2T_h, g_w2T_h); cudaGetSymbolAddress((void**)&w2T_l, g_w2T_l);
    cudaGetSymbolAddress((void**)&w3_h,  g_w3_h ); cudaGetSymbolAddress((void**)&w3_l,  g_w3_l );
    cudaGetSymbolAddress((void**)&G_h,  g_G_h ); cudaGetSymbolAddress((void**)&G_l,  g_G_l );
    cudaGetSymbolAddress((void**)&M2_h, g_M2_h); cudaGetSymbolAddress((void**)&M2_l, g_M2_l);
    cudaGetSymbolAddress((void**)&AsT_h, g_AsT_h); cudaGetSymbolAddress((void**)&AsT_l, g_AsT_l);
    cudaGetSymbolAddress((void**)&WT_h, g_WT_h); cudaGetSymbolAddress((void**)&WT_l, g_WT_l);
    cudaGetSymbolAddress((void**)&L, g_L);

    cudaFuncSetAttribute(gemm_bf16x3<true , true >, cudaFuncAttributeMaxDynamicSharedMemorySize, GEMM_SMEM);
    cudaFuncSetAttribute(gemm_bf16x3<true , false>, cudaFuncAttributeMaxDynamicSharedMemorySize, GEMM_SMEM);
    cudaFuncSetAttribute(gemm_bf16x3<false, false>, cudaFuncAttributeMaxDynamicSharedMemorySize, GEMM_SMEM);
    cudaFuncSetAttribute(softmaxT_split, cudaFuncAttributeMaxDynamicSharedMemorySize, SMX_SMEM);

    dim3 tb(16, 16);
    dim3 blk(160);
    dim3 g512(8, 8, NBZ);    // M = N = 512, 64-tiles
    dim3 gOut(8, 16, NBZ);   // M = 1024, N = 512

    // launch 0-2: splits needed by G
    split_kernel<true, true ><<<dim3(16, 32, NBZ), tb>>>(x, x_h, x_l, xT_h, xT_l, 1024, 512);
    split_kernel<false, true><<<dim3(16, 16, 16), tb>>>(w1, nullptr, nullptr, w1T_h, w1T_l, 512, 512);
    split_kernel<false, true><<<dim3(16, 16, 16), tb>>>(w2, nullptr, nullptr, w2T_h, w2T_l, 512, 512);
    // launch 3 (ncu capture target): G upper triangle (36/64 tiles)
    gemm_bf16x3<true, true ><<<dim3(36, 1, NBZ), blk, GEMM_SMEM>>>(
        xT_h, xT_l, xT_h, xT_l, nullptr, G_h, G_l, 1024, 512, 512, NBZ, NBZ);
    // launch 4: mirror lower triangle of G
    mirror_sym<<<dim3(112, NBZ), tb>>>(G_h, G_l);
    // launch 5: w3 split (needed at launch 9)
    split_kernel<true, false><<<dim3(16, 16, 16), tb>>>(w3, w3_h, w3_l, nullptr, nullptr, 512, 512);
    // launch 6: M2[d'][a] = sum_b w2T[d',b] G[a,b]
    gemm_bf16x3<true, false><<<g512, blk, GEMM_SMEM>>>(
        w2T_h, w2T_l, G_h, G_l, nullptr, M2_h, M2_l, 512, 512, 512, 16, NBZ);
    // launch 7: L[h][d'] = sum_a w1T[h,a] M2[d',a]  (f32 out)
    gemm_bf16x3<false, false><<<g512, blk, GEMM_SMEM>>>(
        w1T_h, w1T_l, M2_h, M2_l, L, nullptr, nullptr, 512, 512, 512, 16, NBZ);
    // launch 8: fused softmax rows + transpose + split -> AsT[d'][h]
    softmaxT_split<<<dim3(16, NBZ), dim3(256), SMX_SMEM>>>(L, AsT_h, AsT_l);
    // launch 9: WT[d'][d] = sum_h AsT[d',h] w3[d,h]
    gemm_bf16x3<true, false><<<g512, blk, GEMM_SMEM>>>(
        AsT_h, AsT_l, w3_h, w3_l, nullptr, WT_h, WT_l, 512, 512, 512, NBZ, 16);
    // launch 10: out[n][d'] = sum_d x[n,d] WT[d',d]  (M=1024)
    gemm_bf16x3<false, false><<<gOut, blk, GEMM_SMEM>>>(
        x_h, x_l, WT_h, WT_l, out, nullptr, nullptr, 512, 1024, 512, NBZ, NBZ);
}